// round 10
// baseline (speedup 1.0000x reference)
#include <cuda_runtime.h>
#include <cuda_bf16.h>
#include <cuda_fp16.h>

// BoundaryLoss: loss = sum_{b,c,d,h,w} Gx(q)^2 + 2*Gy(q)^2 (normalized),
// q = softmax(pred, axis=C) - onehot(target); 2-D sobel per depth slice.
// pred (2,4,96,160,160) f32, target (2,96,160,160) i32.
// Phase 0: cp.async bulk-stage raw tile into smem (no scoreboard stalls).
// Phase 1: softmax from smem -> fp16 q smem.  Phase 2: half2 sobel.

#define BB 2
#define CC 4
#define DD 96
#define HH 160
#define WW 160

#define TH 16                       // output rows per block
#define HALO (TH + 2)               // 18
#define RTILES (HH / TH)            // 10
#define NBLK (BB * DD * RTILES)     // 1920
#define NTHREADS 320
#define NWARP (NTHREADS / 32)
#define PITCHB 336                  // q row pitch bytes: [4 guard][160][4 guard] halfs

#define CHSTR (DD * HH * WW)        // pred channel stride (floats)

// dynamic smem layout (bytes)
#define RAW_PRED_OFF 0                          // 4*18*160*4 = 46080
#define RAW_TGT_OFF  46080                      // 18*160*4   = 11520
#define QSM_OFF      57600                      // 4*18*336   = 24192
#define WSUM_OFF     81792                      // 10 floats  = 40
#define DSUM_OFF     81832                      // 10 doubles = 80
#define FLAG_OFF     81912                      // int
#define SMEM_TOTAL   81920

__device__ float g_partial[NBLK];
__device__ int   g_count = 0;

__device__ __forceinline__ __half2 u2h(unsigned x) {
    return *reinterpret_cast<__half2*>(&x);
}
__device__ __forceinline__ unsigned h2u(__half2 x) {
    return *reinterpret_cast<unsigned*>(&x);
}
__device__ __forceinline__ void cpa16(unsigned daddr, const void* gptr, unsigned sz) {
    asm volatile("cp.async.cg.shared.global [%0], [%1], 16, %2;"
                 :: "r"(daddr), "l"(gptr), "r"(sz) : "memory");
}

__global__ __launch_bounds__(NTHREADS, 2)
void bl_main_kernel(const float* __restrict__ pred,
                    const int*   __restrict__ target,
                    float*       __restrict__ out)
{
    extern __shared__ __align__(16) unsigned char smem[];
    unsigned char* qsm = smem + QSM_OFF;
    float*  warpsum  = (float*)(smem + WSUM_OFF);
    double* dwarpsum = (double*)(smem + DSUM_OFF);
    int*    flag     = (int*)(smem + FLAG_OFF);

    const unsigned smem_u32 = (unsigned)__cvta_generic_to_shared(smem);

    const int blk   = blockIdx.x;
    const int rt    = blk % RTILES;
    const int slice = blk / RTILES;
    const int b     = slice / DD;
    const int d     = slice - b * DD;
    const int h0    = rt * TH;

    const float* pred_bd = pred + (size_t)(b * CC * DD + d) * (HH * WW);
    const int*   tgt_bd  = target + (size_t)slice * (HH * WW);

    const int tid = threadIdx.x;
    const int j0  = tid / 40;           // 0..7
    const int vc  = tid - j0 * 40;      // 0..39

    // ---- Phase 0: cp.async raw tile into smem ----
#define ISSUE_ITEM(J, V)                                                            \
    {                                                                               \
        const int  h_    = h0 + (J) - 1;                                            \
        const bool valid = ((unsigned)h_ < (unsigned)HH);                           \
        const int  hc    = valid ? h_ : 0;                                          \
        const unsigned sz = valid ? 16u : 0u;                                       \
        const float* gp = pred_bd + (size_t)hc * WW + 4 * (V);                      \
        _Pragma("unroll")                                                           \
        for (int ch = 0; ch < CC; ch++) {                                           \
            const unsigned da = smem_u32 + RAW_PRED_OFF                             \
                + ((ch * HALO + (J)) * WW + 4 * (V)) * 4;                           \
            cpa16(da, gp + (size_t)ch * CHSTR, sz);                                 \
        }                                                                           \
        cpa16(smem_u32 + RAW_TGT_OFF + ((J) * WW + 4 * (V)) * 4,                    \
              tgt_bd + (size_t)hc * WW + 4 * (V), sz);                              \
    }

    ISSUE_ITEM(j0, vc);
    ISSUE_ITEM(j0 + 8, vc);
    if (tid < 80) ISSUE_ITEM(j0 + 16, vc);
#undef ISSUE_ITEM
    asm volatile("cp.async.commit_group;" ::: "memory");

    // ---- q guard halfs: zero [0..3] and [164..167] per (c,row) ----
    if (tid < CC * HALO * 2) {
        const int c    = tid / (HALO * 2);
        const int rem  = tid - c * (HALO * 2);
        const int row  = rem >> 1;
        const int side = rem & 1;
        *(uint2*)(qsm + (c * HALO + row) * PITCHB + (side ? 328 : 0)) = make_uint2(0u, 0u);
    }

    asm volatile("cp.async.wait_group 0;" ::: "memory");
    __syncthreads();

    // ---- Phase 1: softmax - onehot from raw smem -> fp16 q smem ----
    const float* praw = (const float*)(smem + RAW_PRED_OFF);
    const int*   traw = (const int*)(smem + RAW_TGT_OFF);

#define DO_ITEM(J, V)                                                               \
    {                                                                               \
        const int  h_    = h0 + (J) - 1;                                            \
        const int  bo_   = 8 + 8 * (V) + (J) * PITCHB;                              \
        if ((unsigned)h_ < (unsigned)HH) {                                          \
            const float4 x0 = *(const float4*)(praw + (0 * HALO + (J)) * WW + 4 * (V)); \
            const float4 x1 = *(const float4*)(praw + (1 * HALO + (J)) * WW + 4 * (V)); \
            const float4 x2 = *(const float4*)(praw + (2 * HALO + (J)) * WW + 4 * (V)); \
            const float4 x3 = *(const float4*)(praw + (3 * HALO + (J)) * WW + 4 * (V)); \
            const int4   t  = *(const int4*)(traw + (J) * WW + 4 * (V));            \
            float4 q0, q1, q2, q3;                                                  \
            {                                                                       \
                float e0 = __expf(x0.x), e1 = __expf(x1.x), e2 = __expf(x2.x), e3 = __expf(x3.x); \
                float r = __frcp_rn(e0 + e1 + e2 + e3);                             \
                q0.x = e0 * r - (t.x == 0); q1.x = e1 * r - (t.x == 1);             \
                q2.x = e2 * r - (t.x == 2); q3.x = e3 * r - (t.x == 3);             \
            }                                                                       \
            {                                                                       \
                float e0 = __expf(x0.y), e1 = __expf(x1.y), e2 = __expf(x2.y), e3 = __expf(x3.y); \
                float r = __frcp_rn(e0 + e1 + e2 + e3);                             \
                q0.y = e0 * r - (t.y == 0); q1.y = e1 * r - (t.y == 1);             \
                q2.y = e2 * r - (t.y == 2); q3.y = e3 * r - (t.y == 3);             \
            }                                                                       \
            {                                                                       \
                float e0 = __expf(x0.z), e1 = __expf(x1.z), e2 = __expf(x2.z), e3 = __expf(x3.z); \
                float r = __frcp_rn(e0 + e1 + e2 + e3);                             \
                q0.z = e0 * r - (t.z == 0); q1.z = e1 * r - (t.z == 1);             \
                q2.z = e2 * r - (t.z == 2); q3.z = e3 * r - (t.z == 3);             \
            }                                                                       \
            {                                                                       \
                float e0 = __expf(x0.w), e1 = __expf(x1.w), e2 = __expf(x2.w), e3 = __expf(x3.w); \
                float r = __frcp_rn(e0 + e1 + e2 + e3);                             \
                q0.w = e0 * r - (t.w == 0); q1.w = e1 * r - (t.w == 1);             \
                q2.w = e2 * r - (t.w == 2); q3.w = e3 * r - (t.w == 3);             \
            }                                                                       \
            *(uint2*)(qsm + 0 * HALO * PITCHB + bo_) =                              \
                make_uint2(h2u(__floats2half2_rn(q0.x, q0.y)), h2u(__floats2half2_rn(q0.z, q0.w))); \
            *(uint2*)(qsm + 1 * HALO * PITCHB + bo_) =                              \
                make_uint2(h2u(__floats2half2_rn(q1.x, q1.y)), h2u(__floats2half2_rn(q1.z, q1.w))); \
            *(uint2*)(qsm + 2 * HALO * PITCHB + bo_) =                              \
                make_uint2(h2u(__floats2half2_rn(q2.x, q2.y)), h2u(__floats2half2_rn(q2.z, q2.w))); \
            *(uint2*)(qsm + 3 * HALO * PITCHB + bo_) =                              \
                make_uint2(h2u(__floats2half2_rn(q3.x, q3.y)), h2u(__floats2half2_rn(q3.z, q3.w))); \
        } else {                                                                    \
            const uint2 z = make_uint2(0u, 0u);                                     \
            *(uint2*)(qsm + 0 * HALO * PITCHB + bo_) = z;                           \
            *(uint2*)(qsm + 1 * HALO * PITCHB + bo_) = z;                           \
            *(uint2*)(qsm + 2 * HALO * PITCHB + bo_) = z;                           \
            *(uint2*)(qsm + 3 * HALO * PITCHB + bo_) = z;                           \
        }                                                                           \
    }

    DO_ITEM(j0, vc);
    DO_ITEM(j0 + 8, vc);
    if (tid < 80) DO_ITEM(j0 + 16, vc);
#undef DO_ITEM
    __syncthreads();

    // ---- Phase 2: separable sobel in packed half2 ----
    // thread -> (class c2, 4-col group g2, 8-row strip s2); 4*40*2 = 320
    const int c2   = tid / 80;
    const int rem2 = tid - c2 * 80;
    const int s2   = rem2 / 40;
    const int g2   = rem2 - s2 * 40;
    const int off2 = 8 * g2;

    const __half2 TWOH = __half2half2(__float2half(2.0f));
    const __half2 ZERO = __half2half2(__float2half(0.0f));
    const unsigned char* rp = qsm + (c2 * HALO + s2 * 8) * PITCHB;

    __half2 pu[2], pv[2], cu[2], cv[2];

#define ROW_UV(RP, U, V)                                                  \
    {                                                                     \
        const unsigned eL = *(const unsigned*)((RP) + 4 + off2);          \
        const uint2    M  = *(const uint2*)((RP) + 8 + off2);             \
        const unsigned eR = *(const unsigned*)((RP) + 16 + off2);         \
        const __half2 S0 = u2h(__byte_perm(eL, M.x, 0x5432));             \
        const __half2 S1 = u2h(__byte_perm(M.x, M.y, 0x5432));            \
        const __half2 S2 = u2h(__byte_perm(M.y, eR, 0x5432));             \
        U[0] = __hfma2(u2h(M.x), TWOH, __hadd2(S0, S1));                  \
        U[1] = __hfma2(u2h(M.y), TWOH, __hadd2(S1, S2));                  \
        V[0] = __hsub2(S1, S0);                                           \
        V[1] = __hsub2(S2, S1);                                           \
    }

    ROW_UV(rp, pu, pv); rp += PITCHB;
    ROW_UV(rp, cu, cv); rp += PITCHB;

    float ax = 0.f, ay = 0.f;
#pragma unroll
    for (int half_blk = 0; half_blk < 2; half_blk++) {
        __half2 axh = ZERO, ayh = ZERO;
#pragma unroll
        for (int k = 0; k < 4; k++) {
            __half2 nu[2], nv[2];
            ROW_UV(rp, nu, nv); rp += PITCHB;
#pragma unroll
            for (int i = 0; i < 2; i++) {
                const __half2 gx = __hfma2(cv[i], TWOH, __hadd2(pv[i], nv[i]));
                const __half2 gy = __hsub2(nu[i], pu[i]);
                axh = __hfma2(gx, gx, axh);
                ayh = __hfma2(gy, gy, ayh);
                pu[i] = cu[i]; pv[i] = cv[i];
                cu[i] = nu[i]; cv[i] = nv[i];
            }
        }
        const float2 fx = __half22float2(axh);
        const float2 fy = __half22float2(ayh);
        ax += fx.x + fx.y;
        ay += fy.x + fy.y;
    }
#undef ROW_UV

    float acc = ax + 2.f * ay;

    // ---- block reduction -> per-block partial ----
#pragma unroll
    for (int o = 16; o > 0; o >>= 1)
        acc += __shfl_down_sync(0xffffffffu, acc, o);
    if ((tid & 31) == 0) warpsum[tid >> 5] = acc;
    __syncthreads();

    if (tid == 0) {
        float sm = 0.f;
#pragma unroll
        for (int i = 0; i < NWARP; i++) sm += warpsum[i];
        g_partial[blk] = sm;
        __threadfence();
        *flag = (atomicAdd(&g_count, 1) == NBLK - 1) ? 1 : 0;
    }
    __syncthreads();

    // ---- last block: final reduction + output + counter reset ----
    if (*flag) {
        double sd = 0.0;
        for (int i = tid; i < NBLK; i += NTHREADS) sd += (double)g_partial[i];
#pragma unroll
        for (int o = 16; o > 0; o >>= 1)
            sd += __shfl_down_sync(0xffffffffu, sd, o);
        if ((tid & 31) == 0) dwarpsum[tid >> 5] = sd;
        __syncthreads();
        if (tid == 0) {
            double tot = 0.0;
#pragma unroll
            for (int i = 0; i < NWARP; i++) tot += dwarpsum[i];
            const double per_tensor = (double)BB * (DD + 2) * (HH + 2) * (WW + 2);
            out[0] = (float)(tot / per_tensor / (double)CC);
            g_count = 0;
        }
    }
}

extern "C" void kernel_launch(void* const* d_in, const int* in_sizes, int n_in,
                              void* d_out, int out_size)
{
    const float* pred   = (const float*)d_in[0];
    const int*   target = (const int*)d_in[1];
    float*       out    = (float*)d_out;

    cudaFuncSetAttribute(bl_main_kernel,
                         cudaFuncAttributeMaxDynamicSharedMemorySize, SMEM_TOTAL);
    bl_main_kernel<<<NBLK, NTHREADS, SMEM_TOTAL>>>(pred, target, out);
}